// round 2
// baseline (speedup 1.0000x reference)
#include <cuda_runtime.h>
#include <cuda_bf16.h>

// Problem: SpatialConsistencyLoss
//   original, enhanced: [32,3,512,512] f32
//   p = avg_pool4(mean_c(orig)) - avg_pool4(mean_c(enh))   [32,128,128]
//   loss[i,j] = sum over 4 dirs of (p[i,j] - p[nbr])^2, zero-padded
// Output: [32,1,128,128] f32 (524288 elems)

#define B 32
#define HP 128           // pooled H
#define WP 128           // pooled W
#define NPOOL (B * HP * WP)   // 524288
#define HIN 512
#define WIN 512
#define CH_STRIDE (HIN * WIN)          // 262144
#define IMG_STRIDE (3 * CH_STRIDE)     // 786432

// Scratch for the pooled difference field (2 MB). Device globals are the
// sanctioned alloc-free scratch mechanism.
__device__ float g_pooled[NPOOL];

__global__ void pool_diff_kernel(const float* __restrict__ orig,
                                 const float* __restrict__ enh) {
    int idx = blockIdx.x * blockDim.x + threadIdx.x;
    if (idx >= NPOOL) return;

    int j = idx & (WP - 1);
    int i = (idx >> 7) & (HP - 1);
    int b = idx >> 14;

    // Base offset of the 4x4 input block for channel 0
    int base0 = b * IMG_STRIDE + (i * 4) * WIN + (j * 4);

    float s = 0.0f;
#pragma unroll
    for (int c = 0; c < 3; ++c) {
        int base = base0 + c * CH_STRIDE;
#pragma unroll
        for (int r = 0; r < 4; ++r) {
            float4 ov = *reinterpret_cast<const float4*>(orig + base + r * WIN);
            float4 ev = *reinterpret_cast<const float4*>(enh  + base + r * WIN);
            s += (ov.x - ev.x) + (ov.y - ev.y) + (ov.z - ev.z) + (ov.w - ev.w);
        }
    }
    g_pooled[idx] = s * (1.0f / 48.0f);   // /3 channels, /16 pool
}

__global__ void loss_kernel(float* __restrict__ out) {
    int idx = blockIdx.x * blockDim.x + threadIdx.x;
    if (idx >= NPOOL) return;

    int j = idx & (WP - 1);
    int i = (idx >> 7) & (HP - 1);

    float c = g_pooled[idx];
    float pl = (j > 0)      ? g_pooled[idx - 1]   : 0.0f;
    float pr = (j < WP - 1) ? g_pooled[idx + 1]   : 0.0f;
    float pu = (i > 0)      ? g_pooled[idx - WP]  : 0.0f;
    float pd = (i < HP - 1) ? g_pooled[idx + WP]  : 0.0f;

    float dl = c - pl;
    float dr = c - pr;
    float du = c - pu;
    float dd = c - pd;

    out[idx] = dl * dl + dr * dr + du * du + dd * dd;
}

extern "C" void kernel_launch(void* const* d_in, const int* in_sizes, int n_in,
                              void* d_out, int out_size) {
    const float* orig = (const float*)d_in[0];
    const float* enh  = (const float*)d_in[1];
    float* out = (float*)d_out;

    const int threads = 256;
    const int blocks = (NPOOL + threads - 1) / threads;   // 2048

    pool_diff_kernel<<<blocks, threads>>>(orig, enh);
    loss_kernel<<<blocks, threads>>>(out);
}

// round 3
// speedup vs baseline: 1.0077x; 1.0077x over previous
#include <cuda_runtime.h>
#include <cuda_bf16.h>

// Problem: SpatialConsistencyLoss
//   original, enhanced: [32,3,512,512] f32
//   p = avg_pool4(mean_c(orig)) - avg_pool4(mean_c(enh))   [32,128,128]
//   loss[i,j] = sum over 4 dirs of (p[i,j] - p[nbr])^2, zero-padded
// Output: [32,1,128,128] f32 (524288 elems)

#define B 32
#define HP 128           // pooled H
#define WP 128           // pooled W
#define NPOOL (B * HP * WP)   // 524288
#define HIN 512
#define WIN 512
#define CH_STRIDE (HIN * WIN)          // 262144
#define IMG_STRIDE (3 * CH_STRIDE)     // 786432

// Scratch for the pooled difference field (2 MB). Device globals are the
// sanctioned alloc-free scratch mechanism.
__device__ float g_pooled[NPOOL];

__global__ void pool_diff_kernel(const float* __restrict__ orig,
                                 const float* __restrict__ enh) {
    int idx = blockIdx.x * blockDim.x + threadIdx.x;
    if (idx >= NPOOL) return;

    int j = idx & (WP - 1);
    int i = (idx >> 7) & (HP - 1);
    int b = idx >> 14;

    // Base offset of the 4x4 input block for channel 0
    int base0 = b * IMG_STRIDE + (i * 4) * WIN + (j * 4);

    float s = 0.0f;
#pragma unroll
    for (int c = 0; c < 3; ++c) {
        int base = base0 + c * CH_STRIDE;
#pragma unroll
        for (int r = 0; r < 4; ++r) {
            float4 ov = *reinterpret_cast<const float4*>(orig + base + r * WIN);
            float4 ev = *reinterpret_cast<const float4*>(enh  + base + r * WIN);
            s += (ov.x - ev.x) + (ov.y - ev.y) + (ov.z - ev.z) + (ov.w - ev.w);
        }
    }
    g_pooled[idx] = s * (1.0f / 48.0f);   // /3 channels, /16 pool
}

__global__ void loss_kernel(float* __restrict__ out) {
    int idx = blockIdx.x * blockDim.x + threadIdx.x;
    if (idx >= NPOOL) return;

    int j = idx & (WP - 1);
    int i = (idx >> 7) & (HP - 1);

    float c = g_pooled[idx];
    float pl = (j > 0)      ? g_pooled[idx - 1]   : 0.0f;
    float pr = (j < WP - 1) ? g_pooled[idx + 1]   : 0.0f;
    float pu = (i > 0)      ? g_pooled[idx - WP]  : 0.0f;
    float pd = (i < HP - 1) ? g_pooled[idx + WP]  : 0.0f;

    float dl = c - pl;
    float dr = c - pr;
    float du = c - pu;
    float dd = c - pd;

    out[idx] = dl * dl + dr * dr + du * du + dd * dd;
}

extern "C" void kernel_launch(void* const* d_in, const int* in_sizes, int n_in,
                              void* d_out, int out_size) {
    const float* orig = (const float*)d_in[0];
    const float* enh  = (const float*)d_in[1];
    float* out = (float*)d_out;

    const int threads = 256;
    const int blocks = (NPOOL + threads - 1) / threads;   // 2048

    pool_diff_kernel<<<blocks, threads>>>(orig, enh);
    loss_kernel<<<blocks, threads>>>(out);
}